// round 5
// baseline (speedup 1.0000x reference)
#include <cuda_runtime.h>

// ---------------- problem constants ----------------
#define Bn    64
#define Tn    4096
#define KPn   67      // keypoints: 25 body + 21 + 21
#define KIN   134     // 2*K input features
#define Dn    256     // hidden
#define Cn    7       // classes
#define TT    64      // timesteps per sub-tile
#define NSUB  4       // sub-tiles per block
#define TBLK  (TT*NSUB)   // 256 timesteps per block
#define POSLD 68      // padded row stride for pos tile (floats, 16B-mult)

// scratch: pooled [B, D] (allocation-free rule -> __device__ global)
__device__ float g_pooled[Bn * Dn];

// length may arrive as int32 or int64 depending on jax x64 config.
// int64 little-endian view as int32: [val,0,val,0,...]; length>=1 and
// <=4096 so L[1]==0 uniquely identifies the int64 layout (in-bounds
// either way: int32 reads L[0..63], int64-view reads L[0..127]).
static __device__ __forceinline__ int get_len(const int* __restrict__ L, int b) {
    return (L[1] == 0) ? L[2 * b] : L[b];
}

static __device__ __forceinline__ unsigned long long pack2(float x) {
    unsigned long long r;
    asm("mov.b64 %0, {%1, %1};" : "=l"(r) : "f"(x));
    return r;
}
static __device__ __forceinline__ void fma2(unsigned long long& d,
                                            unsigned long long a,
                                            unsigned long long b) {
    // packed fp32x2 FMA -> SASS FFMA2 (sm_100+), full fp32 precision
    asm("fma.rn.f32x2 %0, %1, %2, %0;" : "+l"(d) : "l"(a), "l"(b));
}
static __device__ __forceinline__ float2 unpack2(unsigned long long v) {
    float2 f;
    asm("mov.b64 {%0, %1}, %2;" : "=f"(f.x), "=f"(f.y) : "l"(v));
    return f;
}

__global__ void zero_pooled_kernel() {
    int i = blockIdx.x * blockDim.x + threadIdx.x;
    if (i < Bn * Dn) g_pooled[i] = 0.0f;
}

// ---------------------------------------------------------------------------
// Kernel 1: fused gather/gate + GEMM(pos @ W1) + masked max-pool
// grid = (Tn/TBLK, Bn), block = 256.
// Block tile: 64 t x 256 d, per-thread 8t x 8d with f32x2 accumulators
// paired along d. W1 [134][256] resident in smem; pos tile [134][64] rebuilt
// per sub-tile. Blocks fully past length[b] exit immediately (avg ~50% of
// blocks -> halves both FLOPs and HBM traffic vs dense).
// ---------------------------------------------------------------------------
__global__ __launch_bounds__(256, 1)
void gemm_pool_kernel(const float* __restrict__ body,
                      const float* __restrict__ hr,
                      const float* __restrict__ hl,
                      const int*   __restrict__ L,
                      const float* __restrict__ W1,
                      const float* __restrict__ b1)
{
    extern __shared__ float smem[];
    float* W1s  = smem;                    // KIN*Dn    = 34304 floats
    float* poss = smem + KIN * Dn;         // KIN*POSLD = 9112 floats
    float* b1s  = poss + KIN * POSLD;      // Dn

    const int tid = threadIdx.x;
    const int b   = blockIdx.y;
    const int len = get_len(L, b);
    const int t0  = blockIdx.x * TBLK;
    if (t0 >= len) return;                 // uniform per block: safe w/ syncs

    // stage W1 (same layout as global: [k][d], d contiguous) + b1
    {
        const float4* g = reinterpret_cast<const float4*>(W1);
        float4* s = reinterpret_cast<float4*>(W1s);
        #pragma unroll 4
        for (int i = tid; i < KIN * Dn / 4; i += 256) s[i] = g[i];
        b1s[tid] = b1[tid];
    }

    const int tt = tid & 7;    // t-group: owns t_local in [tt*8, tt*8+8)
    const int dg = tid >> 3;   // d-group: owns d in [dg*8, dg*8+8)
    const int d0 = dg << 3;

    float vmax[8];
    #pragma unroll
    for (int j = 0; j < 8; j++) vmax[j] = -3.402823466e38f;

    for (int s = 0; s < NSUB; s++) {
        const int t0s = t0 + s * TT;
        if (t0s >= len) break;             // uniform per block
        __syncthreads();                   // protect poss reuse (also W1 @ s=0)

        // gather + confidence-gate into pos tile, transposed [k][t]
        for (int p = tid; p < TT * KPn; p += 256) {
            const int tl = p / KPn;
            const int kp = p - tl * KPn;
            const size_t t = (size_t)(t0s + tl);
            const float* src;
            if (kp < 25)      src = body + ((size_t)b * Tn + t) * 75 + kp * 3;
            else if (kp < 46) src = hr   + ((size_t)b * Tn + t) * 63 + (kp - 25) * 3;
            else              src = hl   + ((size_t)b * Tn + t) * 63 + (kp - 46) * 3;
            const float x = src[0], y = src[1], c = src[2];
            const float gate = (c > 0.1f) ? 1.0f : 0.0f;
            poss[(2 * kp    ) * POSLD + tl] = x * gate;
            poss[(2 * kp + 1) * POSLD + tl] = y * gate;
        }
        __syncthreads();

        unsigned long long acc[8][4];
        #pragma unroll
        for (int i = 0; i < 8; i++)
            #pragma unroll
            for (int j = 0; j < 4; j++) acc[i][j] = 0ULL;

        #pragma unroll 2
        for (int k = 0; k < KIN; k++) {
            const float4* pr =
                reinterpret_cast<const float4*>(poss + k * POSLD + tt * 8);
            const float4 p0 = pr[0];
            const float4 p1 = pr[1];
            unsigned long long P[8];
            P[0] = pack2(p0.x); P[1] = pack2(p0.y);
            P[2] = pack2(p0.z); P[3] = pack2(p0.w);
            P[4] = pack2(p1.x); P[5] = pack2(p1.y);
            P[6] = pack2(p1.z); P[7] = pack2(p1.w);
            const ulonglong2* wr =
                reinterpret_cast<const ulonglong2*>(W1s + k * Dn + d0);
            const ulonglong2 wa = wr[0];
            const ulonglong2 wb = wr[1];
            unsigned long long W[4] = {wa.x, wa.y, wb.x, wb.y};
            #pragma unroll
            for (int i = 0; i < 8; i++)
                #pragma unroll
                for (int j = 0; j < 4; j++)
                    fma2(acc[i][j], P[i], W[j]);
        }

        // masked running max over this sub-tile (bias/relu deferred)
        int nval = len - t0s; if (nval > TT) nval = TT;
        #pragma unroll
        for (int i = 0; i < 8; i++) {
            if (tt * 8 + i < nval) {
                #pragma unroll
                for (int j = 0; j < 4; j++) {
                    const float2 v = unpack2(acc[i][j]);
                    vmax[2 * j    ] = fmaxf(vmax[2 * j    ], v.x);
                    vmax[2 * j + 1] = fmaxf(vmax[2 * j + 1], v.y);
                }
            }
        }
    }

    // reduce over the 8 t-groups (lanes tt=0..7 within each dg share d-range)
    #pragma unroll
    for (int j = 0; j < 8; j++) {
        vmax[j] = fmaxf(vmax[j], __shfl_xor_sync(0xffffffffu, vmax[j], 1));
        vmax[j] = fmaxf(vmax[j], __shfl_xor_sync(0xffffffffu, vmax[j], 2));
        vmax[j] = fmaxf(vmax[j], __shfl_xor_sync(0xffffffffu, vmax[j], 4));
    }
    if (tt == 0) {
        #pragma unroll
        for (int j = 0; j < 8; j++) {
            // max_t relu(h+b1) = max(0, max_t h + b1); values >= 0 so
            // int-bit atomicMax is exact. -inf + b1 -> clamped to 0, harmless.
            const float val = fmaxf(vmax[j] + b1s[d0 + j], 0.0f);
            atomicMax(reinterpret_cast<int*>(&g_pooled[b * Dn + d0 + j]),
                      __float_as_int(val));
        }
    }
}

// ---------------------------------------------------------------------------
// Kernel 2: BatchNorm (batch stats, two-pass) + classifier. One block of 256
// (tid d-mapping requires blockDim.x == Dn == 256).
// ---------------------------------------------------------------------------
__global__ __launch_bounds__(256, 1)
void bn_cls_kernel(const float* __restrict__ gamma,
                   const float* __restrict__ beta,
                   const float* __restrict__ Wc,
                   const float* __restrict__ bc,
                   float* __restrict__ out)
{
    __shared__ float scale_s[Dn], shift_s[Dn];
    const int tid = threadIdx.x;
    {
        const int d = tid;
        float s = 0.0f;
        #pragma unroll 4
        for (int b = 0; b < Bn; b++) s += g_pooled[b * Dn + d];
        const float mean = s * (1.0f / Bn);
        float v = 0.0f;
        #pragma unroll 4
        for (int b = 0; b < Bn; b++) {
            const float df = g_pooled[b * Dn + d] - mean;
            v += df * df;
        }
        const float var = v * (1.0f / Bn);          // ddof=0, matches jnp.var
        const float sc  = gamma[d] / sqrtf(var + 1e-5f);
        scale_s[d] = sc;
        shift_s[d] = beta[d] - mean * sc;
    }
    __syncthreads();
    for (int idx = tid; idx < Bn * Cn; idx += 256) {
        const int bb = idx / Cn;
        const int c  = idx - bb * Cn;
        float acc = bc[c];
        #pragma unroll 4
        for (int d = 0; d < Dn; d++)
            acc += (g_pooled[bb * Dn + d] * scale_s[d] + shift_s[d])
                   * Wc[d * Cn + c];
        out[idx] = acc;   // idx == bb*7 + c
    }
}

// ---------------------------------------------------------------------------
extern "C" void kernel_launch(void* const* d_in, const int* in_sizes, int n_in,
                              void* d_out, int out_size)
{
    (void)in_sizes; (void)n_in; (void)out_size;
    const float* body  = (const float*)d_in[0];
    const float* hrp   = (const float*)d_in[1];
    const float* hlp   = (const float*)d_in[2];
    const int*   len   = (const int*)d_in[3];
    const float* W1    = (const float*)d_in[4];
    const float* b1    = (const float*)d_in[5];
    const float* gamma = (const float*)d_in[6];
    const float* beta  = (const float*)d_in[7];
    const float* Wc    = (const float*)d_in[8];
    const float* bc    = (const float*)d_in[9];
    float* out = (float*)d_out;

    const int smem1 = (KIN * Dn + KIN * POSLD + Dn) * (int)sizeof(float); // ~174.7KB
    cudaFuncSetAttribute(gemm_pool_kernel,
                         cudaFuncAttributeMaxDynamicSharedMemorySize, smem1);

    zero_pooled_kernel<<<(Bn * Dn + 255) / 256, 256>>>();
    dim3 grid(Tn / TBLK, Bn);
    gemm_pool_kernel<<<grid, 256, smem1>>>(body, hrp, hlp, len, W1, b1);
    bn_cls_kernel<<<1, 256>>>(gamma, beta, Wc, bc, out);
}